// round 3
// baseline (speedup 1.0000x reference)
#include <cuda_runtime.h>
#include <float.h>

// Problem constants
#define D_IN   1024
#define D_OUT  1024
#define BATCH  4096
#define KDIM   3072   // 3 * D_IN  (x^3, x^2, x features)

// ---------------------------------------------------------------------------
// Scratch (static __device__ globals — no runtime allocation allowed).
// NOTE: these are referenced DIRECTLY inside kernels (taking their address in
// host code yields the host shadow symbol — that was the R2 bug).
// ---------------------------------------------------------------------------
__device__ __align__(16) float g_min[D_IN];
__device__ __align__(16) float g_max[D_IN];
__device__ __align__(16) float g_bias[D_OUT];
__device__ __align__(16) float g_W[D_OUT * KDIM];   // [O, K] row-major, K = t*1024 + d
__device__ __align__(16) float g_F[BATCH * KDIM];   // [B, K] row-major

// ---------------------------------------------------------------------------
// Kernel 1: per-column min/max over the batch dim. Also zeroes g_bias.
// grid = 32 blocks, block = (32, 8)
// ---------------------------------------------------------------------------
__global__ void minmax_kernel(const float* __restrict__ x) {
    __shared__ float smin[8][32];
    __shared__ float smax[8][32];
    int tx = threadIdx.x;          // column within group (coalesced)
    int ty = threadIdx.y;          // row-chunk
    int col = blockIdx.x * 32 + tx;

    float vmin = FLT_MAX, vmax = -FLT_MAX;
    for (int r = ty; r < BATCH; r += 8) {
        float v = x[r * D_IN + col];
        vmin = fminf(vmin, v);
        vmax = fmaxf(vmax, v);
    }
    smin[ty][tx] = vmin;
    smax[ty][tx] = vmax;
    __syncthreads();
    if (ty == 0) {
        #pragma unroll
        for (int i = 1; i < 8; i++) {
            vmin = fminf(vmin, smin[i][tx]);
            vmax = fmaxf(vmax, smax[i][tx]);
        }
        g_min[col] = vmin;
        g_max[col] = vmax;
    }
    // zero the bias accumulator (32 blocks * 256 threads = 8192 >= 1024)
    int gid = blockIdx.x * 256 + ty * 32 + tx;
    if (gid < D_OUT) g_bias[gid] = 0.0f;
}

// ---------------------------------------------------------------------------
// Kernel 2: reduce spline coeffs over the 4 spline points.
//   coeffs layout: [O, D, P=4, C=4], element (o,d,p,k) at ((o*D+d)*4+p)*4+k
//   Produces g_W[o*KDIM + t*1024 + d] = sum_p coeffs[o,d,p,t]  for t=0,1,2
//   and g_bias[o] += sum_d sum_p coeffs[o,d,p,3]  (warp-reduced atomics)
// ---------------------------------------------------------------------------
__global__ void coeff_reduce_kernel(const float* __restrict__ coeffs) {
    int gid = blockIdx.x * blockDim.x + threadIdx.x;   // gid = o*1024 + d
    int d = gid & (D_IN - 1);
    int o = gid >> 10;

    const float4* base = reinterpret_cast<const float4*>(coeffs) + (size_t)gid * 4;
    float4 p0 = base[0];
    float4 p1 = base[1];
    float4 p2 = base[2];
    float4 p3 = base[3];

    float s0 = (p0.x + p1.x) + (p2.x + p3.x);   // x^3 coeff
    float s1 = (p0.y + p1.y) + (p2.y + p3.y);   // x^2 coeff
    float s2 = (p0.z + p1.z) + (p2.z + p3.z);   // x   coeff
    float s3 = (p0.w + p1.w) + (p2.w + p3.w);   // const

    int wbase = o * KDIM + d;
    g_W[wbase]            = s0;
    g_W[wbase + D_IN]     = s1;
    g_W[wbase + 2 * D_IN] = s2;

    // warp covers 32 consecutive d within same o (D_IN % 32 == 0)
    #pragma unroll
    for (int off = 16; off > 0; off >>= 1)
        s3 += __shfl_down_sync(0xffffffffu, s3, off);
    if ((threadIdx.x & 31) == 0)
        atomicAdd(&g_bias[o], s3);
}

// ---------------------------------------------------------------------------
// Kernel 3: build the feature matrix F[b, t*1024+d] = xn^(3-t)
// ---------------------------------------------------------------------------
__global__ void features_kernel(const float* __restrict__ x) {
    int gid = blockIdx.x * blockDim.x + threadIdx.x;   // gid = b*1024 + d
    int d = gid & (D_IN - 1);
    int b = gid >> 10;

    float mn = g_min[d];
    float inv = 1.0f / (g_max[d] - mn);
    float xn = (x[gid] - mn) * inv;
    float x2 = xn * xn;
    float x3 = x2 * xn;

    int base = b * KDIM;
    g_F[base + d]            = x3;
    g_F[base + D_IN + d]     = x2;
    g_F[base + 2 * D_IN + d] = xn;
}

// ---------------------------------------------------------------------------
// Kernel 4: SGEMM  C[M,N] = F[M,K] * W[N,K]^T + bias[N]
//   M=4096, N=1024, K=3072.  128x128 block tile, 8x8 thread tile, BK=8.
//   A/B/bias come from the __device__ globals directly.
// grid = (N/128, M/128) = (8, 32), block = 256
// ---------------------------------------------------------------------------
#define BM 128
#define BN 128
#define BK 8
#define SM_PAD 4

__global__ __launch_bounds__(256) void sgemm_kernel(float* __restrict__ C) {
    const int M = BATCH, N = D_OUT, K = KDIM;
    (void)M;

    __shared__ float As[BK][BM + SM_PAD];
    __shared__ float Bs[BK][BN + SM_PAD];

    const int tid = threadIdx.x;
    const int block_m = blockIdx.y * BM;
    const int block_n = blockIdx.x * BN;

    // global->shared load indices: each thread loads one float4 of A and B
    const int ld_row = tid >> 1;           // 0..127
    const int ld_col = (tid & 1) * 4;      // 0 or 4

    // compute indices: 16x16 thread grid, each owns 2x(4) x 2x(4) micro-tiles
    const int tx = tid & 15;
    const int ty = tid >> 4;

    float acc[8][8];
    #pragma unroll
    for (int i = 0; i < 8; i++)
        #pragma unroll
        for (int j = 0; j < 8; j++)
            acc[i][j] = 0.0f;

    const float* Aptr = g_F + (size_t)(block_m + ld_row) * K + ld_col;
    const float* Bptr = g_W + (size_t)(block_n + ld_row) * K + ld_col;

    for (int k0 = 0; k0 < K; k0 += BK) {
        float4 av = *reinterpret_cast<const float4*>(Aptr + k0);
        float4 bv = *reinterpret_cast<const float4*>(Bptr + k0);

        As[ld_col + 0][ld_row] = av.x;
        As[ld_col + 1][ld_row] = av.y;
        As[ld_col + 2][ld_row] = av.z;
        As[ld_col + 3][ld_row] = av.w;

        Bs[ld_col + 0][ld_row] = bv.x;
        Bs[ld_col + 1][ld_row] = bv.y;
        Bs[ld_col + 2][ld_row] = bv.z;
        Bs[ld_col + 3][ld_row] = bv.w;

        __syncthreads();

        #pragma unroll
        for (int kk = 0; kk < BK; kk++) {
            float4 a0 = *reinterpret_cast<const float4*>(&As[kk][ty * 4]);
            float4 a1 = *reinterpret_cast<const float4*>(&As[kk][64 + ty * 4]);
            float4 b0 = *reinterpret_cast<const float4*>(&Bs[kk][tx * 4]);
            float4 b1 = *reinterpret_cast<const float4*>(&Bs[kk][64 + tx * 4]);

            float ar[8] = {a0.x, a0.y, a0.z, a0.w, a1.x, a1.y, a1.z, a1.w};
            float br[8] = {b0.x, b0.y, b0.z, b0.w, b1.x, b1.y, b1.z, b1.w};

            #pragma unroll
            for (int i = 0; i < 8; i++)
                #pragma unroll
                for (int j = 0; j < 8; j++)
                    acc[i][j] = fmaf(ar[i], br[j], acc[i][j]);
        }
        __syncthreads();
    }

    // epilogue: add bias, vectorized stores
    #pragma unroll
    for (int jn = 0; jn < 2; jn++) {
        int n = block_n + jn * 64 + tx * 4;
        float4 bz = *reinterpret_cast<const float4*>(&g_bias[n]);
        #pragma unroll
        for (int im = 0; im < 2; im++) {
            #pragma unroll
            for (int i = 0; i < 4; i++) {
                int m = block_m + im * 64 + ty * 4 + i;
                float4 v;
                v.x = acc[im * 4 + i][jn * 4 + 0] + bz.x;
                v.y = acc[im * 4 + i][jn * 4 + 1] + bz.y;
                v.z = acc[im * 4 + i][jn * 4 + 2] + bz.z;
                v.w = acc[im * 4 + i][jn * 4 + 3] + bz.w;
                *reinterpret_cast<float4*>(&C[(size_t)m * N + n]) = v;
            }
        }
    }
}

// ---------------------------------------------------------------------------
// Launch
// ---------------------------------------------------------------------------
extern "C" void kernel_launch(void* const* d_in, const int* in_sizes, int n_in,
                              void* d_out, int out_size) {
    // Robust input binding: x has 4096*1024 elements, coeffs 1024*1024*16.
    const float* x;
    const float* coeffs;
    if (in_sizes[0] == BATCH * D_IN) {
        x      = (const float*)d_in[0];
        coeffs = (const float*)d_in[1];
    } else {
        coeffs = (const float*)d_in[0];
        x      = (const float*)d_in[1];
    }
    float* out = (float*)d_out;   // [4096, 1024] float32

    // 1. min/max per column (+ zero bias)
    minmax_kernel<<<32, dim3(32, 8)>>>(x);

    // 2. reduce spline coeffs -> W and bias
    coeff_reduce_kernel<<<(D_OUT * D_IN) / 256, 256>>>(coeffs);

    // 3. feature matrix
    features_kernel<<<(BATCH * D_IN) / 256, 256>>>(x);

    // 4. GEMM + bias (reads g_F/g_W/g_bias directly as device globals)
    dim3 grid(D_OUT / BN, BATCH / BM);
    sgemm_kernel<<<grid, 256>>>(out);
}

// round 12
// speedup vs baseline: 2.5751x; 2.5751x over previous
#include <cuda_runtime.h>
#include <cuda_bf16.h>
#include <float.h>
#include <stdint.h>

// ---------------------------------------------------------------------------
// Problem constants
// ---------------------------------------------------------------------------
#define D_IN   1024
#define D_OUT  1024
#define BATCH  4096
#define KSEG   3072              // 3 * D_IN (x^3, x^2, x)
#define KB2    9216              // 3 * KSEG (hi*hi, lo*hi, hi*lo split in K)

// GEMM tiling
#define BM     128
#define BN     128
#define BK     64                // bf16 -> 128 bytes per row
#define STAGES 3
#define ITERS  (KB2 / BK)        // 144
#define STAGE_BYTES (BM * 128 + BN * 128)     // 32 KB
#define SMEM_TOTAL  (STAGES * STAGE_BYTES)    // 96 KB

// ---------------------------------------------------------------------------
// Device scratch (static globals — no runtime allocation)
// ---------------------------------------------------------------------------
__device__ __align__(1024) __nv_bfloat16 g_A2[(size_t)BATCH * KB2]; // [M, K'] bf16
__device__ __align__(1024) __nv_bfloat16 g_B2[(size_t)D_OUT * KB2]; // [N, K'] bf16
__device__ __align__(16) float g_min[D_IN];
__device__ __align__(16) float g_max[D_IN];
__device__ __align__(16) float g_bias[D_OUT];

// ---------------------------------------------------------------------------
// PTX helpers — baseline (non-arch-specific) features only:
//   cp.async (sm_80), ldmatrix (sm_75), mma.sync bf16 (sm_80)
// ---------------------------------------------------------------------------
__device__ __forceinline__ uint32_t smem_u32(const void* p) {
    uint32_t a;
    asm("{ .reg .u64 t; cvta.to.shared.u64 t, %1; cvt.u32.u64 %0, t; }" : "=r"(a) : "l"(p));
    return a;
}
__device__ __forceinline__ void cp_async16(uint32_t saddr, const void* gaddr) {
    asm volatile("cp.async.cg.shared.global [%0], [%1], 16;" :: "r"(saddr), "l"(gaddr) : "memory");
}
#define CP_COMMIT() asm volatile("cp.async.commit_group;" ::: "memory")
#define CP_WAIT(n)  asm volatile("cp.async.wait_group %0;" :: "n"(n) : "memory")

__device__ __forceinline__ void ldsm_x4(uint32_t* r, uint32_t addr) {
    asm volatile("ldmatrix.sync.aligned.m8n8.x4.shared.b16 {%0,%1,%2,%3}, [%4];"
                 : "=r"(r[0]), "=r"(r[1]), "=r"(r[2]), "=r"(r[3]) : "r"(addr));
}
__device__ __forceinline__ void mma_bf16(float* d, const uint32_t* a, const uint32_t* b) {
    asm volatile("mma.sync.aligned.m16n8k16.row.col.f32.bf16.bf16.f32 "
                 "{%0,%1,%2,%3}, {%4,%5,%6,%7}, {%8,%9}, {%0,%1,%2,%3};"
                 : "+f"(d[0]), "+f"(d[1]), "+f"(d[2]), "+f"(d[3])
                 : "r"(a[0]), "r"(a[1]), "r"(a[2]), "r"(a[3]), "r"(b[0]), "r"(b[1]));
}

// ---------------------------------------------------------------------------
// Kernel 1: per-column min/max + zero bias
// ---------------------------------------------------------------------------
__global__ void minmax_kernel(const float* __restrict__ x) {
    __shared__ float smin[8][32];
    __shared__ float smax[8][32];
    int tx = threadIdx.x, ty = threadIdx.y;
    int col = blockIdx.x * 32 + tx;

    float vmin = FLT_MAX, vmax = -FLT_MAX;
    for (int r = ty; r < BATCH; r += 8) {
        float v = x[r * D_IN + col];
        vmin = fminf(vmin, v);
        vmax = fmaxf(vmax, v);
    }
    smin[ty][tx] = vmin;
    smax[ty][tx] = vmax;
    __syncthreads();
    if (ty == 0) {
        #pragma unroll
        for (int i = 1; i < 8; i++) {
            vmin = fminf(vmin, smin[i][tx]);
            vmax = fmaxf(vmax, smax[i][tx]);
        }
        g_min[col] = vmin;
        g_max[col] = vmax;
    }
    int gid = blockIdx.x * 256 + ty * 32 + tx;
    if (gid < D_OUT) g_bias[gid] = 0.0f;
}

// ---------------------------------------------------------------------------
// Kernel 2: spline-coeff reduce -> bf16 hi/lo weight matrix + bias
//   B' row o: seg0 = hi(w_t)  (pairs A_hi)
//             seg1 = hi(w_t)  (pairs A_lo)
//             seg2 = lo(w_t)  (pairs A_hi)
// ---------------------------------------------------------------------------
__global__ void coeff2_kernel(const float* __restrict__ coeffs) {
    int gid = blockIdx.x * blockDim.x + threadIdx.x;   // o*1024 + d
    int d = gid & (D_IN - 1);
    int o = gid >> 10;

    const float4* base = reinterpret_cast<const float4*>(coeffs) + (size_t)gid * 4;
    float4 p0 = base[0], p1 = base[1], p2 = base[2], p3 = base[3];

    float s[3];
    s[0] = (p0.x + p1.x) + (p2.x + p3.x);
    s[1] = (p0.y + p1.y) + (p2.y + p3.y);
    s[2] = (p0.z + p1.z) + (p2.z + p3.z);
    float s3 = (p0.w + p1.w) + (p2.w + p3.w);

    size_t row = (size_t)o * KB2;
    #pragma unroll
    for (int t = 0; t < 3; t++) {
        __nv_bfloat16 h = __float2bfloat16(s[t]);
        __nv_bfloat16 l = __float2bfloat16(s[t] - __bfloat162float(h));
        g_B2[row + t * D_IN + d]            = h;
        g_B2[row + KSEG + t * D_IN + d]     = h;
        g_B2[row + 2 * KSEG + t * D_IN + d] = l;
    }

    #pragma unroll
    for (int off = 16; off > 0; off >>= 1)
        s3 += __shfl_down_sync(0xffffffffu, s3, off);
    if ((threadIdx.x & 31) == 0)
        atomicAdd(&g_bias[o], s3);
}

// ---------------------------------------------------------------------------
// Kernel 3: features -> bf16 hi/lo feature matrix
//   A' row b: seg0 = hi(f_t), seg1 = lo(f_t), seg2 = hi(f_t)
// ---------------------------------------------------------------------------
__global__ void features2_kernel(const float* __restrict__ x) {
    int gid = blockIdx.x * blockDim.x + threadIdx.x;   // b*1024 + d
    int d = gid & (D_IN - 1);
    int b = gid >> 10;

    float mn = g_min[d];
    float inv = 1.0f / (g_max[d] - mn);
    float xn = (x[gid] - mn) * inv;
    float f[3];
    f[1] = xn * xn;
    f[0] = f[1] * xn;
    f[2] = xn;

    size_t row = (size_t)b * KB2;
    #pragma unroll
    for (int t = 0; t < 3; t++) {
        __nv_bfloat16 h = __float2bfloat16(f[t]);
        __nv_bfloat16 l = __float2bfloat16(f[t] - __bfloat162float(h));
        g_A2[row + t * D_IN + d]            = h;
        g_A2[row + KSEG + t * D_IN + d]     = l;
        g_A2[row + 2 * KSEG + t * D_IN + d] = h;
    }
}

// ---------------------------------------------------------------------------
// Kernel 4: bf16 GEMM via mma.sync  C[4096,1024] = A'[4096,K'] B'[1024,K']^T + bias
//   CTA 128x128, BK=64, 3-stage cp.async pipeline, 8 warps 2(M)x4(N),
//   warp tile 64x32 of m16n8k16.
//   SMEM: row = 128 bytes; swizzle: 16B chunk c at row r -> c ^ (r & 7)
// ---------------------------------------------------------------------------
__device__ __forceinline__ void load_stage(uint32_t sA, uint32_t sB,
                                           int m0, int n0, int kbyte, int tid) {
    int row = tid >> 3;        // 0..31
    int c   = tid & 7;         // 16B chunk within 128B row
    const char* gA = (const char*)g_A2;
    const char* gB = (const char*)g_B2;
    #pragma unroll
    for (int j = 0; j < 4; j++) {
        int r = row + j * 32;
        uint32_t sw = (uint32_t)(c ^ (r & 7)) << 4;
        cp_async16(sA + r * 128 + sw,
                   gA + (size_t)(m0 + r) * (KB2 * 2) + kbyte + c * 16);
        cp_async16(sB + r * 128 + sw,
                   gB + (size_t)(n0 + r) * (KB2 * 2) + kbyte + c * 16);
    }
}

__global__ void __launch_bounds__(256, 2) gemm_kernel(float* __restrict__ C) {
    extern __shared__ char smem[];
    const uint32_t sbase = smem_u32(smem);

    const int tid  = threadIdx.x;
    const int lane = tid & 31;
    const int wid  = tid >> 5;
    const int wm   = (wid & 1) * 64;    // warp M offset in CTA tile
    const int wn   = (wid >> 1) * 32;   // warp N offset

    const int m0 = blockIdx.y * BM;
    const int n0 = blockIdx.x * BN;

    float acc[4][4][4];
    #pragma unroll
    for (int i = 0; i < 4; i++)
        #pragma unroll
        for (int j = 0; j < 4; j++)
            #pragma unroll
            for (int k = 0; k < 4; k++)
                acc[i][j][k] = 0.0f;

    // prologue: fill STAGES-1 stages
    #pragma unroll
    for (int s = 0; s < STAGES - 1; s++) {
        uint32_t st = sbase + s * STAGE_BYTES;
        load_stage(st, st + BM * 128, m0, n0, s * 128, tid);
        CP_COMMIT();
    }

    // ldmatrix lane addressing (constant across k-steps except chunk)
    const int a_row_in_tile = lane & 15;       // 0..15
    const int a_half        = lane >> 4;       // 0..1 (k chunk select)
    const int b_g           = lane >> 3;       // 0..3 matrix group
    const int b_row_in_pair = ((b_g >> 1) << 3) + (lane & 7); // 0..15
    const int b_chunk_sel   = b_g & 1;

    for (int it = 0; it < ITERS; it++) {
        CP_WAIT(STAGES - 2);
        __syncthreads();

        uint32_t st = sbase + (it % STAGES) * STAGE_BYTES;
        uint32_t sA = st;
        uint32_t sB = st + BM * 128;

        #pragma unroll
        for (int kk = 0; kk < BK / 16; kk++) {
            uint32_t a_frag[4][4];
            uint32_t b_frag[2][4];
            #pragma unroll
            for (int tm = 0; tm < 4; tm++) {
                int r = wm + tm * 16 + a_row_in_tile;
                int ch = kk * 2 + a_half;
                ldsm_x4(a_frag[tm], sA + r * 128 + ((uint32_t)(ch ^ (r & 7)) << 4));
            }
            #pragma unroll
            for (int tn2 = 0; tn2 < 2; tn2++) {
                int r = wn + tn2 * 16 + b_row_in_pair;
                int ch = kk * 2 + b_chunk_sel;
                ldsm_x4(b_frag[tn2], sB + r * 128 + ((uint32_t)(ch ^ (r & 7)) << 4));
            }
            #pragma unroll
            for (int tm = 0; tm < 4; tm++)
                #pragma unroll
                for (int tn = 0; tn < 4; tn++)
                    mma_bf16(acc[tm][tn], a_frag[tm], &b_frag[tn >> 1][(tn & 1) * 2]);
        }

        __syncthreads();
        // prefetch k-iter it + STAGES - 1 into stage slot (it + STAGES - 1) % STAGES
        int nit = it + STAGES - 1;
        if (nit < ITERS) {
            uint32_t pst = sbase + (nit % STAGES) * STAGE_BYTES;
            load_stage(pst, pst + BM * 128, m0, n0, nit * 128, tid);
        }
        CP_COMMIT();
    }

    // epilogue: bias + store
    #pragma unroll
    for (int tm = 0; tm < 4; tm++) {
        #pragma unroll
        for (int tn = 0; tn < 4; tn++) {
            float* d = acc[tm][tn];
            int r   = m0 + wm + tm * 16 + (lane >> 2);
            int col = n0 + wn + tn * 8 + ((lane & 3) << 1);
            float b0 = g_bias[col];
            float b1 = g_bias[col + 1];
            float2 v0 = make_float2(d[0] + b0, d[1] + b1);
            float2 v1 = make_float2(d[2] + b0, d[3] + b1);
            *reinterpret_cast<float2*>(&C[(size_t)r * D_OUT + col])       = v0;
            *reinterpret_cast<float2*>(&C[(size_t)(r + 8) * D_OUT + col]) = v1;
        }
    }
}

// ---------------------------------------------------------------------------
// Host launch
// ---------------------------------------------------------------------------
extern "C" void kernel_launch(void* const* d_in, const int* in_sizes, int n_in,
                              void* d_out, int out_size) {
    const float* x;
    const float* coeffs;
    if (in_sizes[0] == BATCH * D_IN) {
        x      = (const float*)d_in[0];
        coeffs = (const float*)d_in[1];
    } else {
        coeffs = (const float*)d_in[0];
        x      = (const float*)d_in[1];
    }
    float* out = (float*)d_out;

    cudaFuncSetAttribute(gemm_kernel, cudaFuncAttributeMaxDynamicSharedMemorySize, SMEM_TOTAL);

    minmax_kernel<<<32, dim3(32, 8)>>>(x);
    coeff2_kernel<<<(D_OUT * D_IN) / 256, 256>>>(coeffs);
    features2_kernel<<<(BATCH * D_IN) / 256, 256>>>(x);

    dim3 grid(D_OUT / BN, BATCH / BM);   // (8, 32)
    gemm_kernel<<<grid, 256, SMEM_TOTAL>>>(out);
}

// round 15
// speedup vs baseline: 3.4134x; 1.3256x over previous
#include <cuda_runtime.h>
#include <cuda_fp16.h>
#include <float.h>
#include <stdint.h>

// ---------------------------------------------------------------------------
// Problem constants
// ---------------------------------------------------------------------------
#define D_IN   1024
#define D_OUT  1024
#define BATCH  4096
#define KSEG   3072              // 3 * D_IN (x^3, x^2, x features)
#define KA     6144              // 2 * KSEG : A = [Ah, Al] fp16 exact split
                                 // B is single fp16: C = (Ah+Al)·Bh

// GEMM tiling
#define BM     128
#define BN     128
#define BK     64                // fp16 -> 128 bytes per row-chunk
#define STAGES 3
#define ITERS  (KA / BK)         // 96
#define STAGE_BYTES (BM * 128 + BN * 128)     // 32 KB
#define SMEM_TOTAL  (STAGES * STAGE_BYTES)    // 96 KB

// ---------------------------------------------------------------------------
// Device scratch (static globals — no runtime allocation)
// ---------------------------------------------------------------------------
__device__ __align__(1024) __half g_Ah[(size_t)BATCH * KA];   // [M, 2*KSEG]
__device__ __align__(1024) __half g_Bh[(size_t)D_OUT * KSEG]; // [N, KSEG]
__device__ __align__(16) float g_min[D_IN];
__device__ __align__(16) float g_max[D_IN];
__device__ __align__(16) float g_bias[D_OUT];

// ---------------------------------------------------------------------------
// PTX helpers — baseline features only (cp.async, ldmatrix, mma.sync fp16)
// ---------------------------------------------------------------------------
__device__ __forceinline__ uint32_t smem_u32(const void* p) {
    uint32_t a;
    asm("{ .reg .u64 t; cvta.to.shared.u64 t, %1; cvt.u32.u64 %0, t; }" : "=r"(a) : "l"(p));
    return a;
}
__device__ __forceinline__ void cp_async16(uint32_t saddr, const void* gaddr) {
    asm volatile("cp.async.cg.shared.global [%0], [%1], 16;" :: "r"(saddr), "l"(gaddr) : "memory");
}
#define CP_COMMIT() asm volatile("cp.async.commit_group;" ::: "memory")
#define CP_WAIT(n)  asm volatile("cp.async.wait_group %0;" :: "n"(n) : "memory")

__device__ __forceinline__ void ldsm_x4(uint32_t* r, uint32_t addr) {
    asm volatile("ldmatrix.sync.aligned.m8n8.x4.shared.b16 {%0,%1,%2,%3}, [%4];"
                 : "=r"(r[0]), "=r"(r[1]), "=r"(r[2]), "=r"(r[3]) : "r"(addr));
}
__device__ __forceinline__ void mma_f16(float* d, const uint32_t* a, const uint32_t* b) {
    asm volatile("mma.sync.aligned.m16n8k16.row.col.f32.f16.f16.f32 "
                 "{%0,%1,%2,%3}, {%4,%5,%6,%7}, {%8,%9}, {%0,%1,%2,%3};"
                 : "+f"(d[0]), "+f"(d[1]), "+f"(d[2]), "+f"(d[3])
                 : "r"(a[0]), "r"(a[1]), "r"(a[2]), "r"(a[3]), "r"(b[0]), "r"(b[1]));
}

// ---------------------------------------------------------------------------
// Kernel 1: per-column min/max + zero bias
// ---------------------------------------------------------------------------
__global__ void minmax_kernel(const float* __restrict__ x) {
    __shared__ float smin[8][32];
    __shared__ float smax[8][32];
    int tx = threadIdx.x, ty = threadIdx.y;
    int col = blockIdx.x * 32 + tx;

    float vmin = FLT_MAX, vmax = -FLT_MAX;
    for (int r = ty; r < BATCH; r += 8) {
        float v = x[r * D_IN + col];
        vmin = fminf(vmin, v);
        vmax = fmaxf(vmax, v);
    }
    smin[ty][tx] = vmin;
    smax[ty][tx] = vmax;
    __syncthreads();
    if (ty == 0) {
        #pragma unroll
        for (int i = 1; i < 8; i++) {
            vmin = fminf(vmin, smin[i][tx]);
            vmax = fmaxf(vmax, smax[i][tx]);
        }
        g_min[col] = vmin;
        g_max[col] = vmax;
    }
    int gid = blockIdx.x * 256 + ty * 32 + tx;
    if (gid < D_OUT) g_bias[gid] = 0.0f;
}

// ---------------------------------------------------------------------------
// Kernel 2: spline-coeff reduce -> single fp16 weight matrix + fp32 bias
// ---------------------------------------------------------------------------
__global__ void coeff2_kernel(const float* __restrict__ coeffs) {
    int gid = blockIdx.x * blockDim.x + threadIdx.x;   // o*1024 + d
    int d = gid & (D_IN - 1);
    int o = gid >> 10;

    const float4* base = reinterpret_cast<const float4*>(coeffs) + (size_t)gid * 4;
    float4 p0 = base[0], p1 = base[1], p2 = base[2], p3 = base[3];

    float s[3];
    s[0] = (p0.x + p1.x) + (p2.x + p3.x);
    s[1] = (p0.y + p1.y) + (p2.y + p3.y);
    s[2] = (p0.z + p1.z) + (p2.z + p3.z);
    float s3 = (p0.w + p1.w) + (p2.w + p3.w);

    size_t row = (size_t)o * KSEG;
    #pragma unroll
    for (int t = 0; t < 3; t++)
        g_Bh[row + t * D_IN + d] = __float2half(s[t]);

    #pragma unroll
    for (int off = 16; off > 0; off >>= 1)
        s3 += __shfl_down_sync(0xffffffffu, s3, off);
    if ((threadIdx.x & 31) == 0)
        atomicAdd(&g_bias[o], s3);
}

// ---------------------------------------------------------------------------
// Kernel 3: features -> fp16 exact hi/lo feature matrix
//   A row b: [0,KSEG)   = hi(f_t) at t*1024+d
//            [KSEG,2K)  = lo(f_t) = f_t - hi(f_t)
// ---------------------------------------------------------------------------
__global__ void features2_kernel(const float* __restrict__ x) {
    int gid = blockIdx.x * blockDim.x + threadIdx.x;   // b*1024 + d
    int d = gid & (D_IN - 1);
    int b = gid >> 10;

    float mn = g_min[d];
    float inv = 1.0f / (g_max[d] - mn);
    float xn = (x[gid] - mn) * inv;
    float f[3];
    f[1] = xn * xn;
    f[0] = f[1] * xn;
    f[2] = xn;

    size_t row = (size_t)b * KA;
    #pragma unroll
    for (int t = 0; t < 3; t++) {
        __half h = __float2half(f[t]);
        __half l = __float2half(f[t] - __half2float(h));
        g_Ah[row + t * D_IN + d]        = h;
        g_Ah[row + KSEG + t * D_IN + d] = l;
    }
}

// ---------------------------------------------------------------------------
// Kernel 4: fp16 GEMM via mma.sync
//   C[4096,1024] = (Ah+Al)[4096, 2*KSEG] * Bh[1024, KSEG]^T + bias
//   A k-iter it reads A k-offset it*BK (segments contiguous);
//   B k-offset wraps: (it % 48) * BK  (B traversed twice).
//   CTA 128x128, BK=64, 3-stage cp.async pipeline, one sync per iter,
//   8 warps 2(M)x4(N), warp tile 64x32 of m16n8k16.
//   SMEM row = 128 bytes; swizzle: 16B chunk c at row r -> c ^ (r & 7)
// ---------------------------------------------------------------------------
__device__ __forceinline__ void load_stage(uint32_t st, int m0, int n0, int it, int tid) {
    uint32_t sA = st;
    uint32_t sB = st + BM * 128;
    int row = tid >> 3;        // 0..31
    int c   = tid & 7;         // 16B chunk within 128B row
    int kA_byte = it * (BK * 2);                 // A: linear over 2*KSEG
    int kB_byte = (it >= 48 ? it - 48 : it) * (BK * 2);  // B: wraps at KSEG
    const char* gA = (const char*)g_Ah;
    const char* gB = (const char*)g_Bh;
    #pragma unroll
    for (int j = 0; j < 4; j++) {
        int r = row + j * 32;
        uint32_t sw = (uint32_t)(c ^ (r & 7)) << 4;
        cp_async16(sA + r * 128 + sw,
                   gA + (size_t)(m0 + r) * (KA * 2) + kA_byte + c * 16);
        cp_async16(sB + r * 128 + sw,
                   gB + (size_t)(n0 + r) * (KSEG * 2) + kB_byte + c * 16);
    }
}

__global__ void __launch_bounds__(256, 2) gemm_kernel(float* __restrict__ C) {
    extern __shared__ char smem[];
    const uint32_t sbase = smem_u32(smem);

    const int tid  = threadIdx.x;
    const int lane = tid & 31;
    const int wid  = tid >> 5;
    const int wm   = (wid & 1) * 64;    // warp M offset in CTA tile
    const int wn   = (wid >> 1) * 32;   // warp N offset

    const int m0 = blockIdx.y * BM;
    const int n0 = blockIdx.x * BN;

    float acc[4][4][4];
    #pragma unroll
    for (int i = 0; i < 4; i++)
        #pragma unroll
        for (int j = 0; j < 4; j++)
            #pragma unroll
            for (int k = 0; k < 4; k++)
                acc[i][j][k] = 0.0f;

    // prologue: fill STAGES-1 stages
    #pragma unroll
    for (int s = 0; s < STAGES - 1; s++) {
        load_stage(sbase + s * STAGE_BYTES, m0, n0, s, tid);
        CP_COMMIT();
    }

    // ldmatrix lane addressing
    const int a_row_in_tile = lane & 15;       // 0..15
    const int a_half        = lane >> 4;       // 0..1 (16B k-chunk select)
    const int b_g           = lane >> 3;       // 0..3 matrix group
    const int b_row_in_pair = ((b_g >> 1) << 3) + (lane & 7); // 0..15
    const int b_chunk_sel   = b_g & 1;

    for (int it = 0; it < ITERS; it++) {
        CP_WAIT(STAGES - 2);
        __syncthreads();
        // All warps finished compute(it-1) -> stage (it-1)%STAGES is free.
        // Prefetch k-iter it+STAGES-1 into that slot, overlapping with compute.
        int nit = it + STAGES - 1;
        if (nit < ITERS)
            load_stage(sbase + (nit % STAGES) * STAGE_BYTES, m0, n0, nit, tid);
        CP_COMMIT();

        uint32_t st = sbase + (it % STAGES) * STAGE_BYTES;
        uint32_t sA = st;
        uint32_t sB = st + BM * 128;

        #pragma unroll
        for (int kk = 0; kk < BK / 16; kk++) {
            uint32_t a_frag[4][4];
            uint32_t b_frag[2][4];
            #pragma unroll
            for (int tm = 0; tm < 4; tm++) {
                int r = wm + tm * 16 + a_row_in_tile;
                int ch = kk * 2 + a_half;
                ldsm_x4(a_frag[tm], sA + r * 128 + ((uint32_t)(ch ^ (r & 7)) << 4));
            }
            #pragma unroll
            for (int tn2 = 0; tn2 < 2; tn2++) {
                int r = wn + tn2 * 16 + b_row_in_pair;
                int ch = kk * 2 + b_chunk_sel;
                ldsm_x4(b_frag[tn2], sB + r * 128 + ((uint32_t)(ch ^ (r & 7)) << 4));
            }
            #pragma unroll
            for (int tm = 0; tm < 4; tm++)
                #pragma unroll
                for (int tn = 0; tn < 4; tn++)
                    mma_f16(acc[tm][tn], a_frag[tm], &b_frag[tn >> 1][(tn & 1) * 2]);
        }
    }

    // epilogue: bias + store
    #pragma unroll
    for (int tm = 0; tm < 4; tm++) {
        #pragma unroll
        for (int tn = 0; tn < 4; tn++) {
            float* d = acc[tm][tn];
            int r   = m0 + wm + tm * 16 + (lane >> 2);
            int col = n0 + wn + tn * 8 + ((lane & 3) << 1);
            float b0 = g_bias[col];
            float b1 = g_bias[col + 1];
            float2 v0 = make_float2(d[0] + b0, d[1] + b1);
            float2 v1 = make_float2(d[2] + b0, d[3] + b1);
            *reinterpret_cast<float2*>(&C[(size_t)r * D_OUT + col])       = v0;
            *reinterpret_cast<float2*>(&C[(size_t)(r + 8) * D_OUT + col]) = v1;
        }
    }
}

// ---------------------------------------------------------------------------
// Host launch
// ---------------------------------------------------------------------------
extern "C" void kernel_launch(void* const* d_in, const int* in_sizes, int n_in,
                              void* d_out, int out_size) {
    const float* x;
    const float* coeffs;
    if (in_sizes[0] == BATCH * D_IN) {
        x      = (const float*)d_in[0];
        coeffs = (const float*)d_in[1];
    } else {
        coeffs = (const float*)d_in[0];
        x      = (const float*)d_in[1];
    }
    float* out = (float*)d_out;

    cudaFuncSetAttribute(gemm_kernel, cudaFuncAttributeMaxDynamicSharedMemorySize, SMEM_TOTAL);

    minmax_kernel<<<32, dim3(32, 8)>>>(x);
    coeff2_kernel<<<(D_OUT * D_IN) / 256, 256>>>(coeffs);
    features2_kernel<<<(BATCH * D_IN) / 256, 256>>>(x);

    dim3 grid(D_OUT / BN, BATCH / BM);   // (8, 32)
    gemm_kernel<<<grid, 256, SMEM_TOTAL>>>(out);
}